// round 3
// baseline (speedup 1.0000x reference)
#include <cuda_runtime.h>

#define NUM_LINK 9
#define DOF 7
#define RPB 64            // robots per block (256 threads, 4 per robot)
#define THREADS 256
#define F4_PER_ROBOT (NUM_LINK * 4)       // 36 float4 per robot
#define F4_PER_BLOCK (RPB * F4_PER_ROBOT) // 2304 float4 = 36864 B

__device__ __forceinline__ void stcs_f4(float4* p, float4 v) {
    asm volatile("st.global.cs.v4.f32 [%0], {%1,%2,%3,%4};"
                 :: "l"(p), "f"(v.x), "f"(v.y), "f"(v.z), "f"(v.w) : "memory");
}

// Forward kinematics, 4 threads per robot (one matrix row each), smem-staged
// output so global stores are fully coalesced 512B/warp-instruction.
__global__ __launch_bounds__(THREADS)
void fk_kernel(const float* __restrict__ Tbase,
               const float* __restrict__ Toff,
               const float* __restrict__ Q,
               float* __restrict__ out,
               int B)
{
    __shared__ float4 sToff[NUM_LINK * 4];
    __shared__ float4 sbuf[F4_PER_BLOCK];

    if (threadIdx.x < NUM_LINK * 4)
        sToff[threadIdx.x] = reinterpret_cast<const float4*>(Toff)[threadIdx.x];
    __syncthreads();

    const int t   = threadIdx.x;
    const int rl  = t >> 2;          // robot within block
    const int sub = t & 3;           // row index
    const int b   = blockIdx.x * RPB + rl;
    const int bb  = (b < B) ? b : (B - 1);   // clamp: uniform shfl participation

    // Coalesced Tbase row load (warp covers contiguous 512B).
    float4 r = reinterpret_cast<const float4*>(Tbase)[(size_t)bb * 4 + sub];

    // sincos split over the 4 lanes of this robot; exchange via shfl(width=4).
    const float* qb = Q + (size_t)bb * DOF;
    float s_lo, c_lo, s_hi = 0.f, c_hi = 1.f;
    __sincosf(qb[sub], &s_lo, &c_lo);
    if (sub < 3) __sincosf(qb[sub + 4], &s_hi, &c_hi);

    float sj[DOF], cj[DOF];
    #pragma unroll
    for (int j = 0; j < 4; j++) {
        sj[j] = __shfl_sync(0xFFFFFFFFu, s_lo, j, 4);
        cj[j] = __shfl_sync(0xFFFFFFFFu, c_lo, j, 4);
    }
    #pragma unroll
    for (int j = 4; j < DOF; j++) {
        sj[j] = __shfl_sync(0xFFFFFFFFu, s_hi, j - 4, 4);
        cj[j] = __shfl_sync(0xFFFFFFFFu, c_hi, j - 4, 4);
    }

    #pragma unroll
    for (int i = 0; i < NUM_LINK; i++) {
        // r = r @ Toff[i]  (row-vector times 4x4, rows broadcast from smem)
        float4 o0 = sToff[i * 4 + 0];
        float4 o1 = sToff[i * 4 + 1];
        float4 o2 = sToff[i * 4 + 2];
        float4 o3 = sToff[i * 4 + 3];
        float4 n;
        n.x = fmaf(r.x, o0.x, fmaf(r.y, o1.x, fmaf(r.z, o2.x, r.w * o3.x)));
        n.y = fmaf(r.x, o0.y, fmaf(r.y, o1.y, fmaf(r.z, o2.y, r.w * o3.y)));
        n.z = fmaf(r.x, o0.z, fmaf(r.y, o1.z, fmaf(r.z, o2.z, r.w * o3.z)));
        n.w = fmaf(r.x, o0.w, fmaf(r.y, o1.w, fmaf(r.z, o2.w, r.w * o3.w)));
        r = n;

        // Revolute joint at links 1..7 (axes z,y,z,y,z,y,z): mixes two columns.
        if (i >= 1 && i <= 7) {
            float s = sj[i - 1], c = cj[i - 1];
            if (i & 1) {        // z
                float x = r.x, y = r.y;
                r.x = fmaf(c, x,  s * y);
                r.y = fmaf(c, y, -s * x);
            } else {            // y
                float x = r.x, z = r.z;
                r.x = fmaf(c, x, -s * z);
                r.z = fmaf(c, z,  s * x);
            }
        }

        // Stage into smem (conflict-free STS.128 phases).
        sbuf[rl * F4_PER_ROBOT + i * 4 + sub] = r;
    }

    __syncthreads();

    // Copy out: fully coalesced, streaming stores (don't pollute L2 reads).
    float4* og = reinterpret_cast<float4*>(out);
    const size_t base  = (size_t)blockIdx.x * F4_PER_BLOCK;
    const size_t limit = (size_t)B * F4_PER_ROBOT;
    #pragma unroll
    for (int k = 0; k < NUM_LINK; k++) {
        size_t idx = base + (size_t)k * THREADS + t;
        if (idx < limit)
            stcs_f4(og + idx, sbuf[k * THREADS + t]);
    }
}

extern "C" void kernel_launch(void* const* d_in, const int* in_sizes, int n_in,
                              void* d_out, int out_size)
{
    int B = out_size / (NUM_LINK * 16);

    const float* Tbase = nullptr;
    const float* Toff  = nullptr;
    const float* Q     = nullptr;
    for (int i = 0; i < n_in; i++) {
        if (in_sizes[i] == NUM_LINK * 16)      Toff  = (const float*)d_in[i];
        else if (in_sizes[i] == B * 16)        Tbase = (const float*)d_in[i];
        else if (in_sizes[i] == B * DOF)       Q     = (const float*)d_in[i];
    }
    if (!Tbase) Tbase = (const float*)d_in[0];
    if (!Toff)  Toff  = (const float*)d_in[1];
    if (!Q)     Q     = (const float*)d_in[2];

    float* out = (float*)d_out;

    const int blocks = (B + RPB - 1) / RPB;
    fk_kernel<<<blocks, THREADS>>>(Tbase, Toff, Q, out, B);
}

// round 4
// speedup vs baseline: 1.0866x; 1.0866x over previous
#include <cuda_runtime.h>
#include <cstdint>

#define NUM_LINK 9
#define DOF 7
#define RPB 64            // robots per block (256 threads, 4 per robot)
#define THREADS 256
#define F4_PER_ROBOT (NUM_LINK * 4)       // 36 float4 per robot
#define F4_PER_BLOCK (RPB * F4_PER_ROBOT) // 2304 float4 = 36864 B
#define BYTES_PER_ROBOT (F4_PER_ROBOT * 16)
#define BYTES_PER_BLOCK (F4_PER_BLOCK * 16)

// Forward kinematics, 4 threads per robot (one 4x4 row each).
// Results staged in smem (conflict-free STS), drained by ONE TMA bulk store
// per block: global writes ride the TMA pipe, not the L1 wavefront queue.
__global__ __launch_bounds__(THREADS)
void fk_kernel(const float* __restrict__ Tbase,
               const float* __restrict__ Toff,
               const float* __restrict__ Q,
               float* __restrict__ out,
               int B)
{
    __shared__ float4 sToff[NUM_LINK * 4];
    __shared__ alignas(128) float4 sbuf[F4_PER_BLOCK];

    if (threadIdx.x < NUM_LINK * 4)
        sToff[threadIdx.x] = reinterpret_cast<const float4*>(Toff)[threadIdx.x];
    __syncthreads();

    const int t   = threadIdx.x;
    const int rl  = t >> 2;          // robot within block
    const int sub = t & 3;           // row index
    const int b   = blockIdx.x * RPB + rl;
    const int bb  = (b < B) ? b : (B - 1);   // clamp: uniform shfl participation

    // Coalesced Tbase row load (warp covers contiguous 512B).
    float4 r = reinterpret_cast<const float4*>(Tbase)[(size_t)bb * 4 + sub];

    // sincos split over the 4 lanes of this robot; exchange via shfl(width=4).
    const float* qb = Q + (size_t)bb * DOF;
    float s_lo, c_lo, s_hi = 0.f, c_hi = 1.f;
    __sincosf(qb[sub], &s_lo, &c_lo);
    if (sub < 3) __sincosf(qb[sub + 4], &s_hi, &c_hi);

    float sj[DOF], cj[DOF];
    #pragma unroll
    for (int j = 0; j < 4; j++) {
        sj[j] = __shfl_sync(0xFFFFFFFFu, s_lo, j, 4);
        cj[j] = __shfl_sync(0xFFFFFFFFu, c_lo, j, 4);
    }
    #pragma unroll
    for (int j = 4; j < DOF; j++) {
        sj[j] = __shfl_sync(0xFFFFFFFFu, s_hi, j - 4, 4);
        cj[j] = __shfl_sync(0xFFFFFFFFu, c_hi, j - 4, 4);
    }

    #pragma unroll
    for (int i = 0; i < NUM_LINK; i++) {
        // r = r @ Toff[i]  (row-vector times 4x4, rows broadcast from smem)
        float4 o0 = sToff[i * 4 + 0];
        float4 o1 = sToff[i * 4 + 1];
        float4 o2 = sToff[i * 4 + 2];
        float4 o3 = sToff[i * 4 + 3];
        float4 n;
        n.x = fmaf(r.x, o0.x, fmaf(r.y, o1.x, fmaf(r.z, o2.x, r.w * o3.x)));
        n.y = fmaf(r.x, o0.y, fmaf(r.y, o1.y, fmaf(r.z, o2.y, r.w * o3.y)));
        n.z = fmaf(r.x, o0.z, fmaf(r.y, o1.z, fmaf(r.z, o2.z, r.w * o3.z)));
        n.w = fmaf(r.x, o0.w, fmaf(r.y, o1.w, fmaf(r.z, o2.w, r.w * o3.w)));
        r = n;

        // Revolute joint at links 1..7 (axes z,y,z,y,z,y,z): mixes two columns.
        if (i >= 1 && i <= 7) {
            float s = sj[i - 1], c = cj[i - 1];
            if (i & 1) {        // z
                float x = r.x, y = r.y;
                r.x = fmaf(c, x,  s * y);
                r.y = fmaf(c, y, -s * x);
            } else {            // y
                float x = r.x, z = r.z;
                r.x = fmaf(c, x, -s * z);
                r.z = fmaf(c, z,  s * x);
            }
        }

        // Stage into smem (8-lane phases cover banks 0..31 exactly once).
        sbuf[rl * F4_PER_ROBOT + i * 4 + sub] = r;
    }

    __syncthreads();

    // One TMA bulk store per block: smem -> contiguous global span.
    if (t == 0) {
        int robots_here = B - blockIdx.x * RPB;
        if (robots_here > RPB) robots_here = RPB;
        uint32_t nbytes = (uint32_t)robots_here * BYTES_PER_ROBOT;
        char* gdst = reinterpret_cast<char*>(out) +
                     (size_t)blockIdx.x * BYTES_PER_BLOCK;
        uint32_t saddr = (uint32_t)__cvta_generic_to_shared(sbuf);

        asm volatile("fence.proxy.async.shared::cta;" ::: "memory");
        asm volatile(
            "cp.async.bulk.global.shared::cta.bulk_group [%0], [%1], %2;"
            :: "l"(gdst), "r"(saddr), "r"(nbytes) : "memory");
        asm volatile("cp.async.bulk.commit_group;" ::: "memory");
        asm volatile("cp.async.bulk.wait_group 0;" ::: "memory");
    }
}

extern "C" void kernel_launch(void* const* d_in, const int* in_sizes, int n_in,
                              void* d_out, int out_size)
{
    int B = out_size / (NUM_LINK * 16);

    const float* Tbase = nullptr;
    const float* Toff  = nullptr;
    const float* Q     = nullptr;
    for (int i = 0; i < n_in; i++) {
        if (in_sizes[i] == NUM_LINK * 16)      Toff  = (const float*)d_in[i];
        else if (in_sizes[i] == B * 16)        Tbase = (const float*)d_in[i];
        else if (in_sizes[i] == B * DOF)       Q     = (const float*)d_in[i];
    }
    if (!Tbase) Tbase = (const float*)d_in[0];
    if (!Toff)  Toff  = (const float*)d_in[1];
    if (!Q)     Q     = (const float*)d_in[2];

    float* out = (float*)d_out;

    const int blocks = (B + RPB - 1) / RPB;
    fk_kernel<<<blocks, THREADS>>>(Tbase, Toff, Q, out, B);
}